// round 14
// baseline (speedup 1.0000x reference)
#include <cuda_runtime.h>
#include <cuda_fp16.h>
#include <cstddef>
#include <cstdint>

// Problem constants
#define BB   4
#define PP   1024
#define DD   1024
#define HH   16
#define DQK  64
#define DV   64
#define DMID 4096
#define EPS  1e-5f

// ---------------------------------------------------------------------------
// Scratch: float region + half region (cast), no allocations.
// ---------------------------------------------------------------------------
__device__ float g_scratch[110100480];

// float region (float offsets)
#define OFF_XSA   0            // 4,194,304
#define OFF_X1    4194304      // 4,194,304
#define OFF_Y     8388608      // 4,194,304
#define HALF_BASE 12582912     // halfs start here (float offset)

// half region (half offsets from half base)
#define HO_XH     0            //  4M
#define HO_WQ     4194304      //  1M
#define HO_WK     5242880      //  1M
#define HO_WV     6291456      //  1M
#define HO_WPV    7340032      //  1M
#define HO_W1     8388608      //  4M
#define HO_W2     12582912     //  2M
#define HO_QH     14680064     //  4M
#define HO_KH     18874368     //  4M
#define HO_VT     23068672     //  4M (transposed V: per (b,h) 64x1024)
#define HO_SC     27262976     // 64M (scores, half)
#define HO_ATTNH  94371840     // 64M (attn, half copy)
#define HO_OH     161480704    //  4M
#define HO_X1H    165675008    //  4M
#define HO_HH     169869312    // 16M
#define HO_TH     186646528    //  8M

// ---------------------------------------------------------------------------
// PTX helpers
// ---------------------------------------------------------------------------
__device__ __forceinline__ uint32_t smem_u32(const void* p) {
    return (uint32_t)__cvta_generic_to_shared(p);
}
__device__ __forceinline__ void cp_async16(uint32_t dst, const void* src) {
    asm volatile("cp.async.cg.shared.global [%0], [%1], 16;\n" :: "r"(dst), "l"(src));
}
__device__ __forceinline__ void cp_commit() {
    asm volatile("cp.async.commit_group;\n");
}
template <int N>
__device__ __forceinline__ void cp_wait() {
    asm volatile("cp.async.wait_group %0;\n" :: "n"(N));
}
__device__ __forceinline__ void mma_f16(float& c0, float& c1, float& c2, float& c3,
                                        uint32_t a0, uint32_t a1, uint32_t a2, uint32_t a3,
                                        uint32_t b0, uint32_t b1) {
    asm volatile(
        "mma.sync.aligned.m16n8k16.row.col.f32.f16.f16.f32 "
        "{%0,%1,%2,%3},{%4,%5,%6,%7},{%8,%9},{%0,%1,%2,%3};\n"
        : "+f"(c0), "+f"(c1), "+f"(c2), "+f"(c3)
        : "r"(a0), "r"(a1), "r"(a2), "r"(a3), "r"(b0), "r"(b1));
}
__device__ __forceinline__ void ldsm_x4(uint32_t& r0, uint32_t& r1,
                                        uint32_t& r2, uint32_t& r3, uint32_t addr) {
    asm volatile("ldmatrix.sync.aligned.m8n8.x4.shared.b16 {%0,%1,%2,%3}, [%4];\n"
                 : "=r"(r0), "=r"(r1), "=r"(r2), "=r"(r3) : "r"(addr));
}

// ---------------------------------------------------------------------------
// Prep: merged float -> half copies. Segments by blockIdx.x.
// ---------------------------------------------------------------------------
__global__ __launch_bounds__(256)
void h_copy_all(const float* __restrict__ x,
                const float* __restrict__ wq, const float* __restrict__ wk,
                const float* __restrict__ wv, const float* __restrict__ wpv,
                const float* __restrict__ w1, const float* __restrict__ w2,
                __half* __restrict__ hb)
{
    const int blk = blockIdx.x;
    const float* src;
    __half* dst;
    int seg0;
    if (blk < 4096)       { src = x;   dst = hb + HO_XH;  seg0 = 0; }
    else if (blk < 5120)  { src = wq;  dst = hb + HO_WQ;  seg0 = 4096; }
    else if (blk < 6144)  { src = wk;  dst = hb + HO_WK;  seg0 = 5120; }
    else if (blk < 7168)  { src = wv;  dst = hb + HO_WV;  seg0 = 6144; }
    else if (blk < 8192)  { src = wpv; dst = hb + HO_WPV; seg0 = 7168; }
    else if (blk < 12288) { src = w1;  dst = hb + HO_W1;  seg0 = 8192; }
    else                  { src = w2;  dst = hb + HO_W2;  seg0 = 12288; }
    const int i = (blk - seg0) * 256 + threadIdx.x;
    const float4 v = ((const float4*)src)[i];
    __half2* d = (__half2*)dst;
    d[2 * i]     = __floats2half2_rn(v.x, v.y);
    d[2 * i + 1] = __floats2half2_rn(v.z, v.w);
}

// ---------------------------------------------------------------------------
// FP16 tensor-core GEMM (NT): C = alpha * A @ B^T (+bias)
// CTA 128 x BN x 32(halfs), 3-stage cp.async, 8 warps, ldmatrix operand fetch.
// Swizzle: row r = 4 x 16B chunks; chunk c stored at c^((r>>1)&3).
// EPI: 0 = float out, 1 = half out, 2 = V-transpose half out (smem-staged).
// ---------------------------------------------------------------------------
template <int BN, int EPI>
__global__ __launch_bounds__(256, 2)
void tgemm_h(const __half* __restrict__ A, const __half* __restrict__ B,
             const float* __restrict__ bias, void* __restrict__ Cv,
             int K, int lda, int ldb, int ldc,
             int div,
             long long aOuter, long long aInner,
             long long bOuter, long long bInner,
             long long cOuter, long long cInner,
             float alpha)
{
    constexpr int BM = 128;
    constexpr int STAGES = 3;
    constexpr int NJ = BN / 16;
    constexpr int ASZ = BM * 32;
    constexpr int BSZ = BN * 32;
    constexpr int TLD = 132;           // EPI2 staging row stride (halfs)

    const int z = blockIdx.z;
    A += (long long)(z / div) * aOuter + (long long)(z % div) * aInner;
    B += (long long)(z / div) * bOuter + (long long)(z % div) * bInner;
    const long long coff = (long long)(z / div) * cOuter + (long long)(z % div) * cInner;

    extern __shared__ __half smh[];
    __half* Asm = smh;
    __half* Bsm = smh + STAGES * ASZ;

    const int tid  = threadIdx.x;
    const int lane = tid & 31;
    const int warp = tid >> 5;
    const int warp_m = (warp >> 1) * 32;
    const int warp_n = (warp & 1) * (BN / 2);
    const int m0 = blockIdx.y * BM;
    const int n0 = blockIdx.x * BN;
    const int Kiters = K / 32;

    const uint32_t a_base = smem_u32(Asm);
    const uint32_t b_base = smem_u32(Bsm);

    auto issue_stage = [&](int it) {
        if (it < Kiters) {
            const int s  = it % STAGES;
            const int k0 = it * 32;
#pragma unroll
            for (int i = 0; i < 2; i++) {
                const int idx = tid + i * 256;
                const int r = idx >> 2;
                const int c = idx & 3;
                const int cs = c ^ ((r >> 1) & 3);
                cp_async16(a_base + (uint32_t)(s * ASZ + r * 32 + cs * 8) * 2,
                           A + (size_t)(m0 + r) * lda + k0 + c * 8);
            }
#pragma unroll
            for (int i = 0; i < BN / 64; i++) {
                const int idx = tid + i * 256;
                const int r = idx >> 2;
                const int c = idx & 3;
                const int cs = c ^ ((r >> 1) & 3);
                cp_async16(b_base + (uint32_t)(s * BSZ + r * 32 + cs * 8) * 2,
                           B + (size_t)(n0 + r) * ldb + k0 + c * 8);
            }
        }
        cp_commit();
    };

    float acc[2][NJ][4];
#pragma unroll
    for (int mi = 0; mi < 2; mi++)
#pragma unroll
        for (int nj = 0; nj < NJ; nj++)
#pragma unroll
            for (int c = 0; c < 4; c++) acc[mi][nj][c] = 0.f;

    issue_stage(0);
    issue_stage(1);

    const int e = lane & 3;
    const int qd = lane >> 2;

    // Per-lane ldmatrix address components.
    // A x4 matrices: {r+0,g0},{r+8,g0},{r+0,g1},{r+8,g1} -> af[0..3]
    //   lanes 0-7 m0, 8-15 m1, 16-23 m2, 24-31 m3.
    const int l7      = lane & 7;
    const int aj_row8 = ((lane >> 3) & 1) * 8;   // +8 row for m1/m3
    const int aj_ch   = (lane >> 4) & 1;         // chunk+1 for m2/m3
    // B x4 matrices: {nj,g0},{nj,g1},{nj+1,g0},{nj+1,g1}
    const int bj_ch   = (lane >> 3) & 1;
    const int bj_nj   = (lane >> 4) & 1;

    int ar[2], asw[2];
#pragma unroll
    for (int mi = 0; mi < 2; mi++) {
        ar[mi]  = warp_m + mi * 16 + aj_row8 + l7;
        asw[mi] = (ar[mi] >> 1) & 3;
    }
    int br[NJ / 2], bsw[NJ / 2];
#pragma unroll
    for (int p = 0; p < NJ / 2; p++) {
        br[p]  = warp_n + (p * 2 + bj_nj) * 8 + l7;
        bsw[p] = (br[p] >> 1) & 3;
    }

    for (int it = 0; it < Kiters; ++it) {
        cp_wait<1>();
        __syncthreads();
        issue_stage(it + 2);

        const uint32_t a_st = a_base + (uint32_t)((it % STAGES) * ASZ) * 2;
        const uint32_t b_st = b_base + (uint32_t)((it % STAGES) * BSZ) * 2;

#pragma unroll
        for (int ks = 0; ks < 2; ks++) {
            uint32_t af[2][4];
#pragma unroll
            for (int mi = 0; mi < 2; mi++)
                ldsm_x4(af[mi][0], af[mi][1], af[mi][2], af[mi][3],
                        a_st + (uint32_t)(ar[mi] * 64 +
                                (((2 * ks + aj_ch) ^ asw[mi]) << 4)));
            uint32_t bf[NJ][2];
#pragma unroll
            for (int p = 0; p < NJ / 2; p++)
                ldsm_x4(bf[2 * p][0], bf[2 * p][1], bf[2 * p + 1][0], bf[2 * p + 1][1],
                        b_st + (uint32_t)(br[p] * 64 +
                                (((2 * ks + bj_ch) ^ bsw[p]) << 4)));
#pragma unroll
            for (int mi = 0; mi < 2; mi++)
#pragma unroll
                for (int nj = 0; nj < NJ; nj++)
                    mma_f16(acc[mi][nj][0], acc[mi][nj][1], acc[mi][nj][2], acc[mi][nj][3],
                            af[mi][0], af[mi][1], af[mi][2], af[mi][3],
                            bf[nj][0], bf[nj][1]);
        }
        __syncthreads();
    }

    // ---- epilogue ----
    if (EPI == 2) {
        __half* sst = smh;
#pragma unroll
        for (int mi = 0; mi < 2; mi++) {
#pragma unroll
            for (int nj = 0; nj < NJ; nj++) {
                const int lrow = warp_m + mi * 16 + qd;
                const int lcol = warp_n + nj * 8 + e * 2;
                *(__half2*)&sst[lrow * TLD + lcol] =
                    __floats2half2_rn(acc[mi][nj][0], acc[mi][nj][1]);
                *(__half2*)&sst[(lrow + 8) * TLD + lcol] =
                    __floats2half2_rn(acc[mi][nj][2], acc[mi][nj][3]);
            }
        }
        __syncthreads();
        __half* vt = (__half*)Cv;
        const int b  = m0 >> 10;
        const int t0 = m0 & 1023;
#pragma unroll
        for (int cc = 0; cc < 16; cc++) {
            const int col  = warp * 16 + cc;       // local column in tile
            const int gcol = n0 + col;             // global column
            const int h = gcol >> 6, d = gcol & 63;
            __half hv[4];
#pragma unroll
            for (int j = 0; j < 4; j++)
                hv[j] = sst[(lane * 4 + j) * TLD + col];
            __half* dst = vt + (size_t)((b * 16 + h) * 65536 + (d << 10) + t0 + lane * 4);
            *(uint2*)dst = *(uint2*)hv;
        }
        return;
    }
#pragma unroll
    for (int mi = 0; mi < 2; mi++) {
#pragma unroll
        for (int nj = 0; nj < NJ; nj++) {
            const int row0 = m0 + warp_m + mi * 16 + qd;
            const int col  = n0 + warp_n + nj * 8 + e * 2;
            float v00 = acc[mi][nj][0] * alpha;
            float v01 = acc[mi][nj][1] * alpha;
            float v10 = acc[mi][nj][2] * alpha;
            float v11 = acc[mi][nj][3] * alpha;
            if (bias) {
                const float b0 = bias[col], b1 = bias[col + 1];
                v00 += b0; v01 += b1;
                v10 += b0; v11 += b1;
            }
            if (EPI == 0) {
                float* C = (float*)Cv + coff;
                *(float2*)&C[(size_t)row0 * ldc + col] = make_float2(v00, v01);
                *(float2*)&C[(size_t)(row0 + 8) * ldc + col] = make_float2(v10, v11);
            } else {
                __half* C = (__half*)Cv + coff;
                *(__half2*)&C[(size_t)row0 * ldc + col] = __floats2half2_rn(v00, v01);
                *(__half2*)&C[(size_t)(row0 + 8) * ldc + col] = __floats2half2_rn(v10, v11);
            }
        }
    }
}

// ---------------------------------------------------------------------------
// Head-mix + attn_prev + softmax v4 (R13 proven): register-resident scores,
// g in groups of 4, batched reductions.
// ---------------------------------------------------------------------------
__global__ __launch_bounds__(512, 2)
void mix_softmax_kernel(const __half* __restrict__ scores,
                        const float* __restrict__ attn_prev,
                        const float* __restrict__ W_th,
                        float* __restrict__ attn,
                        __half* __restrict__ attnh)
{
    __shared__ float s_w[256];
    __shared__ float s_m[4][16];
    __shared__ float s_s[4][16];
    __shared__ float s_fm[4];
    __shared__ float s_fs[4];

    const int tid = threadIdx.x;       // 0..511
    const int bq  = blockIdx.x;
    const int b   = bq >> 10;
    const int q   = bq & 1023;
    const int lane = tid & 31;
    const int warp = tid >> 5;

    if (tid < 256) s_w[tid] = W_th[tid];

    float2 sc2[16];
    const __half2* sb = (const __half2*)(scores + (size_t)b * 16777216 +
                                         (size_t)q * 1024);
#pragma unroll
    for (int h = 0; h < 16; h++)
        sc2[h] = __half22float2(sb[(size_t)h * 524288 + tid]);
    __syncthreads();

#pragma unroll
    for (int g0 = 0; g0 < 16; g0 += 4) {
        float vx[4], vy[4];
#pragma unroll
        for (int j = 0; j < 4; j++) {
            const size_t rb = ((size_t)(b * 16 + g0 + j) * 1024 + q) * 1024;
            const float2 pv = *(const float2*)(attn_prev + rb + 2 * tid);
            vx[j] = pv.x;
            vy[j] = pv.y;
        }
#pragma unroll
        for (int h = 0; h < 16; h++) {
#pragma unroll
            for (int j = 0; j < 4; j++) {
                const float w = s_w[(g0 + j) * 16 + h];
                vx[j] = fmaf(w, sc2[h].x, vx[j]);
                vy[j] = fmaf(w, sc2[h].y, vy[j]);
            }
        }

#pragma unroll
        for (int j = 0; j < 4; j++) {
            float mx = fmaxf(vx[j], vy[j]);
#pragma unroll
            for (int o = 16; o; o >>= 1)
                mx = fmaxf(mx, __shfl_xor_sync(0xffffffffu, mx, o));
            if (lane == 0) s_m[j][warp] = mx;
        }
        __syncthreads();
        if (warp < 4) {
            float v = (lane < 16) ? s_m[warp][lane] : -1e30f;
#pragma unroll
            for (int o = 8; o; o >>= 1)
                v = fmaxf(v, __shfl_xor_sync(0xffffffffu, v, o));
            if (lane == 0) s_fm[warp] = v;
        }
        __syncthreads();

#pragma unroll
        for (int j = 0; j < 4; j++) {
            vx[j] = __expf(vx[j] - s_fm[j]);
            vy[j] = __expf(vy[j] - s_fm[j]);
            float s = vx[j] + vy[j];
#pragma unroll
            for (int o = 16; o; o >>= 1)
                s += __shfl_xor_sync(0xffffffffu, s, o);
            if (lane == 0) s_s[j][warp] = s;
        }
        __syncthreads();
        if (warp < 4) {
            float v = (lane < 16) ? s_s[warp][lane] : 0.f;
#pragma unroll
            for (int o = 8; o; o >>= 1)
                v += __shfl_xor_sync(0xffffffffu, v, o);
            if (lane == 0) s_fs[warp] = v;
        }
        __syncthreads();

#pragma unroll
        for (int j = 0; j < 4; j++) {
            const size_t rb = ((size_t)(b * 16 + g0 + j) * 1024 + q) * 1024;
            const float inv = 1.0f / s_fs[j];
            const float ax = vx[j] * inv;
            const float ay = vy[j] * inv;
            *(float2*)(attn + rb + 2 * tid) = make_float2(ax, ay);
            *(__half2*)(attnh + rb + 2 * tid) = __floats2half2_rn(ax, ay);
        }
        __syncthreads();
    }
}

// ---------------------------------------------------------------------------
// out = LayerNorm(a + b)*g + beta. MODE 1: also write half copy.
// ---------------------------------------------------------------------------
template <int MODE>
__global__ __launch_bounds__(256)
void add_ln_kernel(const float* __restrict__ a, const float* __restrict__ b,
                   const float* __restrict__ gam, const float* __restrict__ bet,
                   float* __restrict__ out, __half* __restrict__ outh)
{
    __shared__ float s_red[8];
    __shared__ float s_red2[8];
    const int row = blockIdx.x;
    const int tid = threadIdx.x;
    const int lane = tid & 31, warp = tid >> 5;

    const float4 va = ((const float4*)(a + (size_t)row * 1024))[tid];
    const float4 vb = ((const float4*)(b + (size_t)row * 1024))[tid];
    float4 v;
    v.x = va.x + vb.x; v.y = va.y + vb.y; v.z = va.z + vb.z; v.w = va.w + vb.w;

    float s  = v.x + v.y + v.z + v.w;
    float s2 = v.x * v.x + v.y * v.y + v.z * v.z + v.w * v.w;
#pragma unroll
    for (int o = 16; o; o >>= 1) {
        s  += __shfl_xor_sync(0xffffffffu, s, o);
        s2 += __shfl_xor_sync(0xffffffffu, s2, o);
    }
    if (lane == 0) { s_red[warp] = s; s_red2[warp] = s2; }
    __syncthreads();
    float ts = 0.f, ts2 = 0.f;
#pragma unroll
    for (int w = 0; w < 8; w++) { ts += s_red[w]; ts2 += s_red2[w]; }

    const float mu  = ts * (1.0f / 1024.0f);
    const float var = ts2 * (1.0f / 1024.0f) - mu * mu;
    const float inv = rsqrtf(var + EPS);

    const float4 g4 = ((const float4*)gam)[tid];
    const float4 b4 = ((const float4*)bet)[tid];
    float4 o;
    o.x = (v.x - mu) * inv * g4.x + b4.x;
    o.y = (v.y - mu) * inv * g4.y + b4.y;
    o.z = (v.z - mu) * inv * g4.z + b4.z;
    o.w = (v.w - mu) * inv * g4.w + b4.w;
    ((float4*)(out + (size_t)row * 1024))[tid] = o;
    if (MODE == 1) {
        __half2* hd = (__half2*)(outh + (size_t)row * 1024);
        hd[2 * tid]     = __floats2half2_rn(o.x, o.y);
        hd[2 * tid + 1] = __floats2half2_rn(o.z, o.w);
    }
}

// ---------------------------------------------------------------------------
// GLU on half: t[r][j] = h[r][j] * relu(h[r][2048+j])
// ---------------------------------------------------------------------------
__global__ __launch_bounds__(256)
void glu_kernel(const __half* __restrict__ h, __half* __restrict__ t)
{
    const int i = blockIdx.x * 256 + threadIdx.x;
    const int r = i >> 10;
    const int j = i & 1023;
    const __half2* h2 = (const __half2*)h;
    const float2 a = __half22float2(h2[(size_t)r * 2048 + j]);
    const float2 g = __half22float2(h2[(size_t)r * 2048 + 1024 + j]);
    const float2 o = make_float2(a.x * fmaxf(g.x, 0.f), a.y * fmaxf(g.y, 0.f));
    ((__half2*)t)[(size_t)r * 1024 + j] = __floats2half2_rn(o.x, o.y);
}

// ---------------------------------------------------------------------------
// Launcher
// ---------------------------------------------------------------------------
extern "C" void kernel_launch(void* const* d_in, const int* in_sizes, int n_in,
                              void* d_out, int out_size)
{
    const float* x         = (const float*)d_in[0];
    const float* attn_prev = (const float*)d_in[1];
    const float* Wq        = (const float*)d_in[2];
    const float* Wk        = (const float*)d_in[3];
    const float* Wv        = (const float*)d_in[4];
    const float* W_th      = (const float*)d_in[5];
    const float* Wpv       = (const float*)d_in[6];
    const float* W1        = (const float*)d_in[7];
    const float* b1        = (const float*)d_in[8];
    const float* W2        = (const float*)d_in[9];
    const float* b2        = (const float*)d_in[10];
    const float* ln1g      = (const float*)d_in[11];
    const float* ln1b      = (const float*)d_in[12];
    const float* ln2g      = (const float*)d_in[13];
    const float* ln2b      = (const float*)d_in[14];

    float* out  = (float*)d_out;
    float* attn = out + (size_t)BB * PP * DD;

    float* s = nullptr;
    cudaGetSymbolAddress((void**)&s, g_scratch);
    float* xsa = s + OFF_XSA;
    float* x1  = s + OFF_X1;
    float* yb  = s + OFF_Y;
    __half* hb = (__half*)(s + HALF_BASE);
    __half* xh    = hb + HO_XH;
    __half* wqh   = hb + HO_WQ;
    __half* wkh   = hb + HO_WK;
    __half* wvh   = hb + HO_WV;
    __half* wpvh  = hb + HO_WPV;
    __half* w1h   = hb + HO_W1;
    __half* w2h   = hb + HO_W2;
    __half* qh    = hb + HO_QH;
    __half* kh    = hb + HO_KH;
    __half* vt    = hb + HO_VT;
    __half* sch   = hb + HO_SC;
    __half* attnh = hb + HO_ATTNH;
    __half* oh    = hb + HO_OH;
    __half* x1h   = hb + HO_X1H;
    __half* hh    = hb + HO_HH;
    __half* th    = hb + HO_TH;

    const int SM128 = 3 * (128 * 32 + 128 * 32) * 2;   // 49152
    const int SM64  = 3 * (128 * 32 + 64 * 32) * 2;    // 36864
    cudaFuncSetAttribute((const void*)tgemm_h<128, 0>,
                         cudaFuncAttributeMaxDynamicSharedMemorySize, SM128);
    cudaFuncSetAttribute((const void*)tgemm_h<128, 1>,
                         cudaFuncAttributeMaxDynamicSharedMemorySize, SM128);
    cudaFuncSetAttribute((const void*)tgemm_h<128, 2>,
                         cudaFuncAttributeMaxDynamicSharedMemorySize, SM128);
    cudaFuncSetAttribute((const void*)tgemm_h<64, 1>,
                         cudaFuncAttributeMaxDynamicSharedMemorySize, SM64);

    const int M = BB * PP;          // 4096
    const long long zero = 0;

    // ---- prep: one merged fp32->fp16 conversion kernel ----
    h_copy_all<<<14336, 256>>>(x, Wq, Wk, Wv, Wpv, W1, W2, hb);

    // 1-3: Q (alpha=0.125) -> qh, K -> kh, V -> vt (transposed)
    {
        dim3 grid(DD / 128, M / 128, 1);
        tgemm_h<128, 1><<<grid, 256, SM128>>>(xh, wqh, nullptr, qh,
            DD, DD, DD, HH * DQK,
            1, zero, zero, zero, zero, zero, zero, 0.125f);
        tgemm_h<128, 1><<<grid, 256, SM128>>>(xh, wkh, nullptr, kh,
            DD, DD, DD, HH * DQK,
            1, zero, zero, zero, zero, zero, zero, 1.0f);
        tgemm_h<128, 2><<<grid, 256, SM128>>>(xh, wvh, nullptr, vt,
            DD, DD, DD, 0,
            1, zero, zero, zero, zero, zero, zero, 1.0f);
    }

    // 4: scores[b,h] = q_bh @ k_bh^T  -> sch (half), batched over 64
    {
        dim3 grid(PP / 128, PP / 128, BB * HH);
        tgemm_h<128, 1><<<grid, 256, SM128>>>(qh, kh, nullptr, sch,
            DQK, HH * DQK, HH * DQK, PP,
            HH,
            (long long)PP * 1024, (long long)DQK,
            (long long)PP * 1024, (long long)DQK,
            (long long)HH * PP * PP, (long long)PP * PP,
            1.0f);
    }

    // 5: mix + prev + softmax -> attn (fp32, d_out) + attnh (half)
    mix_softmax_kernel<<<BB * PP, 512>>>(sch, attn_prev, W_th, attn, attnh);

    // 6: o[b,h] = attn_bh @ vt_bh^T  (NT, BN=64) -> oh (half)
    {
        dim3 grid(1, PP / 128, BB * HH);
        tgemm_h<64, 1><<<grid, 256, SM64>>>(attnh, vt, nullptr, oh,
            PP, PP, PP, HH * DV,
            HH,
            (long long)HH * PP * PP, (long long)PP * PP,
            (long long)HH * DV * PP, (long long)DV * PP,
            (long long)PP * 1024, (long long)DV,
            1.0f);
    }

    // 7: x_sa = o @ Wpv^T  -> float
    {
        dim3 grid(DD / 128, M / 128, 1);
        tgemm_h<128, 0><<<grid, 256, SM128>>>(oh, wpvh, nullptr, xsa,
            HH * DV, HH * DV, HH * DV, DD,
            1, zero, zero, zero, zero, zero, zero, 1.0f);
    }

    // 8: x1 = LN(x + xsa) -> float + half
    add_ln_kernel<1><<<M, 256>>>(x, xsa, ln1g, ln1b, x1, x1h);

    // 9: h = x1 @ W1^T + b1 -> hh (half)
    {
        dim3 grid(DMID / 128, M / 128, 1);
        tgemm_h<128, 1><<<grid, 256, SM128>>>(x1h, w1h, b1, hh,
            DD, DD, DD, DMID,
            1, zero, zero, zero, zero, zero, zero, 1.0f);
    }

    // 10: GLU -> th (half)
    glu_kernel<<<16384, 256>>>(hh, th);

    // 11: y = t @ W2^T + b2 -> float
    {
        dim3 grid(DD / 128, M / 128, 1);
        tgemm_h<128, 0><<<grid, 256, SM128>>>(th, w2h, b2, yb,
            DMID / 2, DMID / 2, DMID / 2, DD,
            1, zero, zero, zero, zero, zero, zero, 1.0f);
    }

    // 12: out = LN(x1 + y)
    add_ln_kernel<0><<<M, 256>>>(x1, yb, ln2g, ln2b, out, nullptr);
}

// round 15
// speedup vs baseline: 1.3709x; 1.3709x over previous
#include <cuda_runtime.h>
#include <cuda_fp16.h>
#include <cstddef>
#include <cstdint>

// Problem constants
#define BB   4
#define PP   1024
#define DD   1024
#define HH   16
#define DQK  64
#define DV   64
#define DMID 4096
#define EPS  1e-5f

// ---------------------------------------------------------------------------
// Scratch: float region + half region (cast) + b1r tail, no allocations.
// ---------------------------------------------------------------------------
__device__ float g_scratch[110104576];

// float region (float offsets)
#define OFF_XSA   0            // 4,194,304
#define OFF_X1    4194304      // 4,194,304
#define OFF_Y     8388608      // 4,194,304
#define HALF_BASE 12582912     // halfs start here (float offset)
#define OFF_B1R   110100480    // 4,096 floats (reordered b1)

// half region (half offsets from half base)
#define HO_XH     0            //  4M
#define HO_WQ     4194304      //  1M
#define HO_WK     5242880      //  1M
#define HO_WV     6291456      //  1M
#define HO_WPV    7340032      //  1M
#define HO_W1     8388608      //  4M (pair-interleaved rows)
#define HO_W2     12582912     //  2M
#define HO_QH     14680064     //  4M
#define HO_KH     18874368     //  4M
#define HO_VT     23068672     //  4M (transposed V: per (b,h) 64x1024)
#define HO_SC     27262976     // 64M (scores, half)
#define HO_ATTNH  94371840     // 64M (attn, half copy)
#define HO_OH     161480704    //  4M
#define HO_X1H    165675008    //  4M
#define HO_HH     169869312    // 16M (unused now)
#define HO_TH     186646528    //  8M

// ---------------------------------------------------------------------------
// PTX helpers
// ---------------------------------------------------------------------------
__device__ __forceinline__ uint32_t smem_u32(const void* p) {
    return (uint32_t)__cvta_generic_to_shared(p);
}
__device__ __forceinline__ void cp_async16(uint32_t dst, const void* src) {
    asm volatile("cp.async.cg.shared.global [%0], [%1], 16;\n" :: "r"(dst), "l"(src));
}
__device__ __forceinline__ void cp_commit() {
    asm volatile("cp.async.commit_group;\n");
}
template <int N>
__device__ __forceinline__ void cp_wait() {
    asm volatile("cp.async.wait_group %0;\n" :: "n"(N));
}
__device__ __forceinline__ void mma_f16(float& c0, float& c1, float& c2, float& c3,
                                        uint32_t a0, uint32_t a1, uint32_t a2, uint32_t a3,
                                        uint32_t b0, uint32_t b1) {
    asm volatile(
        "mma.sync.aligned.m16n8k16.row.col.f32.f16.f16.f32 "
        "{%0,%1,%2,%3},{%4,%5,%6,%7},{%8,%9},{%0,%1,%2,%3};\n"
        : "+f"(c0), "+f"(c1), "+f"(c2), "+f"(c3)
        : "r"(a0), "r"(a1), "r"(a2), "r"(a3), "r"(b0), "r"(b1));
}

// ---------------------------------------------------------------------------
// Prep: merged float -> half copies + W1 pair-interleave + b1 reorder.
// Segments by blockIdx.x:
//  [0,4096) x | [4096,5120) Wq | [5120,6144) Wk | [6144,7168) Wv
//  [7168,8192) Wpv | [8192,12288) W1 (interleaved) | [12288,14336) W2
//  [14336,14344) b1 reorder
// ---------------------------------------------------------------------------
__global__ __launch_bounds__(256)
void h_copy_all(const float* __restrict__ x,
                const float* __restrict__ wq, const float* __restrict__ wk,
                const float* __restrict__ wv, const float* __restrict__ wpv,
                const float* __restrict__ w1, const float* __restrict__ w2,
                const float* __restrict__ b1,
                __half* __restrict__ hb, float* __restrict__ b1r)
{
    const int blk = blockIdx.x;
    if (blk >= 14336) {
        // b1 reorder: b1r[2j]=b1[j], b1r[2j+1]=b1[j+2048]
        const int j = (blk - 14336) * 256 + threadIdx.x;   // 0..2047
        b1r[2 * j]     = b1[j];
        b1r[2 * j + 1] = b1[j + 2048];
        return;
    }
    if (blk >= 8192 && blk < 12288) {
        // W1 pair-interleave: dst row 2j = src row j, dst row 2j+1 = src row j+2048
        const int i = (blk - 8192) * 256 + threadIdx.x;    // f4 index, 256 per row
        const int jsrc = i >> 8;
        const int f    = i & 255;
        const int jdst = (jsrc < 2048) ? (2 * jsrc) : (2 * (jsrc - 2048) + 1);
        const float4 v = ((const float4*)w1)[i];
        __half2* d = (__half2*)(hb + HO_W1);
        d[jdst * 512 + 2 * f]     = __floats2half2_rn(v.x, v.y);
        d[jdst * 512 + 2 * f + 1] = __floats2half2_rn(v.z, v.w);
        return;
    }
    const float* src;
    __half* dst;
    int seg0;
    if (blk < 4096)       { src = x;   dst = hb + HO_XH;  seg0 = 0; }
    else if (blk < 5120)  { src = wq;  dst = hb + HO_WQ;  seg0 = 4096; }
    else if (blk < 6144)  { src = wk;  dst = hb + HO_WK;  seg0 = 5120; }
    else if (blk < 7168)  { src = wv;  dst = hb + HO_WV;  seg0 = 6144; }
    else if (blk < 8192)  { src = wpv; dst = hb + HO_WPV; seg0 = 7168; }
    else                  { src = w2;  dst = hb + HO_W2;  seg0 = 12288; }
    const int i = (blk - seg0) * 256 + threadIdx.x;
    const float4 v = ((const float4*)src)[i];
    __half2* d = (__half2*)dst;
    d[2 * i]     = __floats2half2_rn(v.x, v.y);
    d[2 * i + 1] = __floats2half2_rn(v.z, v.w);
}

// ---------------------------------------------------------------------------
// FP16 tensor-core GEMM (NT): C = alpha * A @ B^T (+bias)
// CTA 128 x BN x 32(halfs), 3-stage cp.async, 8 warps, scalar-LDS operand
// fetch (R13-proven). Swizzle: row r = 4 x 16B chunks; chunk c at c^((r>>1)&3).
// EPI: 0 = float out, 1 = half out, 2 = V-transpose half out (smem-staged),
//      4 = GLU on pair-interleaved N: t[.,col/2] = (a+ba)*relu(g+bg), half out.
// ---------------------------------------------------------------------------
template <int BN, int EPI>
__global__ __launch_bounds__(256, 2)
void tgemm_h(const __half* __restrict__ A, const __half* __restrict__ B,
             const float* __restrict__ bias, void* __restrict__ Cv,
             int K, int lda, int ldb, int ldc,
             int div,
             long long aOuter, long long aInner,
             long long bOuter, long long bInner,
             long long cOuter, long long cInner,
             float alpha)
{
    constexpr int BM = 128;
    constexpr int STAGES = 3;
    constexpr int NJ = BN / 16;
    constexpr int ASZ = BM * 32;
    constexpr int BSZ = BN * 32;
    constexpr int TLD = 132;           // EPI2 staging row stride (halfs)

    const int z = blockIdx.z;
    A += (long long)(z / div) * aOuter + (long long)(z % div) * aInner;
    B += (long long)(z / div) * bOuter + (long long)(z % div) * bInner;
    const long long coff = (long long)(z / div) * cOuter + (long long)(z % div) * cInner;

    extern __shared__ __half smh[];
    __half* Asm = smh;
    __half* Bsm = smh + STAGES * ASZ;

    const int tid  = threadIdx.x;
    const int lane = tid & 31;
    const int warp = tid >> 5;
    const int warp_m = (warp >> 1) * 32;
    const int warp_n = (warp & 1) * (BN / 2);
    const int m0 = blockIdx.y * BM;
    const int n0 = blockIdx.x * BN;
    const int Kiters = K / 32;

    const uint32_t a_base = smem_u32(Asm);
    const uint32_t b_base = smem_u32(Bsm);

    auto issue_stage = [&](int it) {
        if (it < Kiters) {
            const int s  = it % STAGES;
            const int k0 = it * 32;
#pragma unroll
            for (int i = 0; i < 2; i++) {
                const int idx = tid + i * 256;
                const int r = idx >> 2;
                const int c = idx & 3;
                const int cs = c ^ ((r >> 1) & 3);
                cp_async16(a_base + (uint32_t)(s * ASZ + r * 32 + cs * 8) * 2,
                           A + (size_t)(m0 + r) * lda + k0 + c * 8);
            }
#pragma unroll
            for (int i = 0; i < BN / 64; i++) {
                const int idx = tid + i * 256;
                const int r = idx >> 2;
                const int c = idx & 3;
                const int cs = c ^ ((r >> 1) & 3);
                cp_async16(b_base + (uint32_t)(s * BSZ + r * 32 + cs * 8) * 2,
                           B + (size_t)(n0 + r) * ldb + k0 + c * 8);
            }
        }
        cp_commit();
    };

    float acc[2][NJ][4];
#pragma unroll
    for (int mi = 0; mi < 2; mi++)
#pragma unroll
        for (int nj = 0; nj < NJ; nj++)
#pragma unroll
            for (int c = 0; c < 4; c++) acc[mi][nj][c] = 0.f;

    issue_stage(0);
    issue_stage(1);

    const int e = lane & 3;
    const int qd = lane >> 2;

    for (int it = 0; it < Kiters; ++it) {
        cp_wait<1>();
        __syncthreads();
        issue_stage(it + 2);

        const uint32_t* as2 = (const uint32_t*)(Asm + (it % STAGES) * ASZ);
        const uint32_t* bs2 = (const uint32_t*)(Bsm + (it % STAGES) * BSZ);

#pragma unroll
        for (int ks = 0; ks < 2; ks++) {
            uint32_t af[2][4];
#pragma unroll
            for (int mi = 0; mi < 2; mi++) {
                const int r0 = warp_m + mi * 16 + qd;
                const int r1 = r0 + 8;
                const int s0 = (r0 >> 1) & 3;
                const int s1 = (r1 >> 1) & 3;
                af[mi][0] = as2[r0 * 16 + (((2 * ks)     ^ s0) << 2) + e];
                af[mi][1] = as2[r1 * 16 + (((2 * ks)     ^ s1) << 2) + e];
                af[mi][2] = as2[r0 * 16 + (((2 * ks + 1) ^ s0) << 2) + e];
                af[mi][3] = as2[r1 * 16 + (((2 * ks + 1) ^ s1) << 2) + e];
            }
            uint32_t bf[NJ][2];
#pragma unroll
            for (int nj = 0; nj < NJ; nj++) {
                const int n = warp_n + nj * 8 + qd;
                const int sn = (n >> 1) & 3;
                bf[nj][0] = bs2[n * 16 + (((2 * ks)     ^ sn) << 2) + e];
                bf[nj][1] = bs2[n * 16 + (((2 * ks + 1) ^ sn) << 2) + e];
            }
#pragma unroll
            for (int mi = 0; mi < 2; mi++)
#pragma unroll
                for (int nj = 0; nj < NJ; nj++)
                    mma_f16(acc[mi][nj][0], acc[mi][nj][1], acc[mi][nj][2], acc[mi][nj][3],
                            af[mi][0], af[mi][1], af[mi][2], af[mi][3],
                            bf[nj][0], bf[nj][1]);
        }
        __syncthreads();
    }

    // ---- epilogue ----
    if (EPI == 4) {
        // GLU on pair-interleaved columns: col even = a, col+1 = g.
        __half* C = (__half*)Cv;
#pragma unroll
        for (int mi = 0; mi < 2; mi++) {
#pragma unroll
            for (int nj = 0; nj < NJ; nj++) {
                const int row0 = m0 + warp_m + mi * 16 + qd;
                const int col  = n0 + warp_n + nj * 8 + e * 2;
                const float ba = bias[col];
                const float bg = bias[col + 1];
                const int tcol = col >> 1;
                const float t0 = (acc[mi][nj][0] + ba) * fmaxf(acc[mi][nj][1] + bg, 0.f);
                const float t1 = (acc[mi][nj][2] + ba) * fmaxf(acc[mi][nj][3] + bg, 0.f);
                C[(size_t)row0 * ldc + tcol]       = __float2half_rn(t0);
                C[(size_t)(row0 + 8) * ldc + tcol] = __float2half_rn(t1);
            }
        }
        return;
    }
    if (EPI == 2) {
        __half* sst = smh;
#pragma unroll
        for (int mi = 0; mi < 2; mi++) {
#pragma unroll
            for (int nj = 0; nj < NJ; nj++) {
                const int lrow = warp_m + mi * 16 + qd;
                const int lcol = warp_n + nj * 8 + e * 2;
                *(__half2*)&sst[lrow * TLD + lcol] =
                    __floats2half2_rn(acc[mi][nj][0], acc[mi][nj][1]);
                *(__half2*)&sst[(lrow + 8) * TLD + lcol] =
                    __floats2half2_rn(acc[mi][nj][2], acc[mi][nj][3]);
            }
        }
        __syncthreads();
        __half* vt = (__half*)Cv;
        const int b  = m0 >> 10;
        const int t0 = m0 & 1023;
#pragma unroll
        for (int cc = 0; cc < 16; cc++) {
            const int col  = warp * 16 + cc;       // local column in tile
            const int gcol = n0 + col;             // global column
            const int h = gcol >> 6, d = gcol & 63;
            __half hv[4];
#pragma unroll
            for (int j = 0; j < 4; j++)
                hv[j] = sst[(lane * 4 + j) * TLD + col];
            __half* dst = vt + (size_t)((b * 16 + h) * 65536 + (d << 10) + t0 + lane * 4);
            *(uint2*)dst = *(uint2*)hv;
        }
        return;
    }
#pragma unroll
    for (int mi = 0; mi < 2; mi++) {
#pragma unroll
        for (int nj = 0; nj < NJ; nj++) {
            const int row0 = m0 + warp_m + mi * 16 + qd;
            const int col  = n0 + warp_n + nj * 8 + e * 2;
            float v00 = acc[mi][nj][0] * alpha;
            float v01 = acc[mi][nj][1] * alpha;
            float v10 = acc[mi][nj][2] * alpha;
            float v11 = acc[mi][nj][3] * alpha;
            if (bias) {
                const float b0 = bias[col], b1 = bias[col + 1];
                v00 += b0; v01 += b1;
                v10 += b0; v11 += b1;
            }
            if (EPI == 0) {
                float* C = (float*)Cv + coff;
                *(float2*)&C[(size_t)row0 * ldc + col] = make_float2(v00, v01);
                *(float2*)&C[(size_t)(row0 + 8) * ldc + col] = make_float2(v10, v11);
            } else {
                __half* C = (__half*)Cv + coff;
                *(__half2*)&C[(size_t)row0 * ldc + col] = __floats2half2_rn(v00, v01);
                *(__half2*)&C[(size_t)(row0 + 8) * ldc + col] = __floats2half2_rn(v10, v11);
            }
        }
    }
}

// ---------------------------------------------------------------------------
// Head-mix + attn_prev + softmax v4 (R13 proven): register-resident scores,
// g in groups of 4, batched reductions.
// ---------------------------------------------------------------------------
__global__ __launch_bounds__(512, 2)
void mix_softmax_kernel(const __half* __restrict__ scores,
                        const float* __restrict__ attn_prev,
                        const float* __restrict__ W_th,
                        float* __restrict__ attn,
                        __half* __restrict__ attnh)
{
    __shared__ float s_w[256];
    __shared__ float s_m[4][16];
    __shared__ float s_s[4][16];
    __shared__ float s_fm[4];
    __shared__ float s_fs[4];

    const int tid = threadIdx.x;       // 0..511
    const int bq  = blockIdx.x;
    const int b   = bq >> 10;
    const int q   = bq & 1023;
    const int lane = tid & 31;
    const int warp = tid >> 5;

    if (tid < 256) s_w[tid] = W_th[tid];

    float2 sc2[16];
    const __half2* sb = (const __half2*)(scores + (size_t)b * 16777216 +
                                         (size_t)q * 1024);
#pragma unroll
    for (int h = 0; h < 16; h++)
        sc2[h] = __half22float2(sb[(size_t)h * 524288 + tid]);
    __syncthreads();

#pragma unroll
    for (int g0 = 0; g0 < 16; g0 += 4) {
        float vx[4], vy[4];
#pragma unroll
        for (int j = 0; j < 4; j++) {
            const size_t rb = ((size_t)(b * 16 + g0 + j) * 1024 + q) * 1024;
            const float2 pv = *(const float2*)(attn_prev + rb + 2 * tid);
            vx[j] = pv.x;
            vy[j] = pv.y;
        }
#pragma unroll
        for (int h = 0; h < 16; h++) {
#pragma unroll
            for (int j = 0; j < 4; j++) {
                const float w = s_w[(g0 + j) * 16 + h];
                vx[j] = fmaf(w, sc2[h].x, vx[j]);
                vy[j] = fmaf(w, sc2[h].y, vy[j]);
            }
        }

#pragma unroll
        for (int j = 0; j < 4; j++) {
            float mx = fmaxf(vx[j], vy[j]);
#pragma unroll
            for (int o = 16; o; o >>= 1)
                mx = fmaxf(mx, __shfl_xor_sync(0xffffffffu, mx, o));
            if (lane == 0) s_m[j][warp] = mx;
        }
        __syncthreads();
        if (warp < 4) {
            float v = (lane < 16) ? s_m[warp][lane] : -1e30f;
#pragma unroll
            for (int o = 8; o; o >>= 1)
                v = fmaxf(v, __shfl_xor_sync(0xffffffffu, v, o));
            if (lane == 0) s_fm[warp] = v;
        }
        __syncthreads();

#pragma unroll
        for (int j = 0; j < 4; j++) {
            vx[j] = __expf(vx[j] - s_fm[j]);
            vy[j] = __expf(vy[j] - s_fm[j]);
            float s = vx[j] + vy[j];
#pragma unroll
            for (int o = 16; o; o >>= 1)
                s += __shfl_xor_sync(0xffffffffu, s, o);
            if (lane == 0) s_s[j][warp] = s;
        }
        __syncthreads();
        if (warp < 4) {
            float v = (lane < 16) ? s_s[warp][lane] : 0.f;
#pragma unroll
            for (int o = 8; o; o >>= 1)
                v += __shfl_xor_sync(0xffffffffu, v, o);
            if (lane == 0) s_fs[warp] = v;
        }
        __syncthreads();

#pragma unroll
        for (int j = 0; j < 4; j++) {
            const size_t rb = ((size_t)(b * 16 + g0 + j) * 1024 + q) * 1024;
            const float inv = 1.0f / s_fs[j];
            const float ax = vx[j] * inv;
            const float ay = vy[j] * inv;
            *(float2*)(attn + rb + 2 * tid) = make_float2(ax, ay);
            *(__half2*)(attnh + rb + 2 * tid) = __floats2half2_rn(ax, ay);
        }
        __syncthreads();
    }
}

// ---------------------------------------------------------------------------
// out = LayerNorm(a + b)*g + beta. MODE 1: also write half copy.
// ---------------------------------------------------------------------------
template <int MODE>
__global__ __launch_bounds__(256)
void add_ln_kernel(const float* __restrict__ a, const float* __restrict__ b,
                   const float* __restrict__ gam, const float* __restrict__ bet,
                   float* __restrict__ out, __half* __restrict__ outh)
{
    __shared__ float s_red[8];
    __shared__ float s_red2[8];
    const int row = blockIdx.x;
    const int tid = threadIdx.x;
    const int lane = tid & 31, warp = tid >> 5;

    const float4 va = ((const float4*)(a + (size_t)row * 1024))[tid];
    const float4 vb = ((const float4*)(b + (size_t)row * 1024))[tid];
    float4 v;
    v.x = va.x + vb.x; v.y = va.y + vb.y; v.z = va.z + vb.z; v.w = va.w + vb.w;

    float s  = v.x + v.y + v.z + v.w;
    float s2 = v.x * v.x + v.y * v.y + v.z * v.z + v.w * v.w;
#pragma unroll
    for (int o = 16; o; o >>= 1) {
        s  += __shfl_xor_sync(0xffffffffu, s, o);
        s2 += __shfl_xor_sync(0xffffffffu, s2, o);
    }
    if (lane == 0) { s_red[warp] = s; s_red2[warp] = s2; }
    __syncthreads();
    float ts = 0.f, ts2 = 0.f;
#pragma unroll
    for (int w = 0; w < 8; w++) { ts += s_red[w]; ts2 += s_red2[w]; }

    const float mu  = ts * (1.0f / 1024.0f);
    const float var = ts2 * (1.0f / 1024.0f) - mu * mu;
    const float inv = rsqrtf(var + EPS);

    const float4 g4 = ((const float4*)gam)[tid];
    const float4 b4 = ((const float4*)bet)[tid];
    float4 o;
    o.x = (v.x - mu) * inv * g4.x + b4.x;
    o.y = (v.y - mu) * inv * g4.y + b4.y;
    o.z = (v.z - mu) * inv * g4.z + b4.z;
    o.w = (v.w - mu) * inv * g4.w + b4.w;
    ((float4*)(out + (size_t)row * 1024))[tid] = o;
    if (MODE == 1) {
        __half2* hd = (__half2*)(outh + (size_t)row * 1024);
        hd[2 * tid]     = __floats2half2_rn(o.x, o.y);
        hd[2 * tid + 1] = __floats2half2_rn(o.z, o.w);
    }
}

// ---------------------------------------------------------------------------
// Launcher
// ---------------------------------------------------------------------------
extern "C" void kernel_launch(void* const* d_in, const int* in_sizes, int n_in,
                              void* d_out, int out_size)
{
    const float* x         = (const float*)d_in[0];
    const float* attn_prev = (const float*)d_in[1];
    const float* Wq        = (const float*)d_in[2];
    const float* Wk        = (const float*)d_in[3];
    const float* Wv        = (const float*)d_in[4];
    const float* W_th      = (const float*)d_in[5];
    const float* Wpv       = (const float*)d_in[6];
    const float* W1        = (const float*)d_in[7];
    const float* b1        = (const float*)d_in[8];
    const float* W2        = (const float*)d_in[9];
    const float* b2        = (const float*)d_in[10];
    const float* ln1g      = (const float*)d_in[11];
    const float* ln1b      = (const float*)d_in[12];
    const float* ln2g      = (const float*)d_in[13];
    const float* ln2b      = (const float*)d_in[14];

    float* out  = (float*)d_out;
    float* attn = out + (size_t)BB * PP * DD;

    float* s = nullptr;
    cudaGetSymbolAddress((void**)&s, g_scratch);
    float* xsa = s + OFF_XSA;
    float* x1  = s + OFF_X1;
    float* yb  = s + OFF_Y;
    float* b1r = s + OFF_B1R;
    __half* hb = (__half*)(s + HALF_BASE);
    __half* xh    = hb + HO_XH;
    __half* wqh   = hb + HO_WQ;
    __half* wkh   = hb + HO_WK;
    __half* wvh   = hb + HO_WV;
    __half* wpvh  = hb + HO_WPV;
    __half* w1h   = hb + HO_W1;
    __half* w2h   = hb + HO_W2;
    __half* qh    = hb + HO_QH;
    __half* kh    = hb + HO_KH;
    __half* vt    = hb + HO_VT;
    __half* sch   = hb + HO_SC;
    __half* attnh = hb + HO_ATTNH;
    __half* oh    = hb + HO_OH;
    __half* x1h   = hb + HO_X1H;
    __half* th    = hb + HO_TH;

    const int SM128 = 3 * (128 * 32 + 128 * 32) * 2;   // 49152
    const int SM64  = 3 * (128 * 32 + 64 * 32) * 2;    // 36864
    cudaFuncSetAttribute((const void*)tgemm_h<128, 0>,
                         cudaFuncAttributeMaxDynamicSharedMemorySize, SM128);
    cudaFuncSetAttribute((const void*)tgemm_h<128, 1>,
                         cudaFuncAttributeMaxDynamicSharedMemorySize, SM128);
    cudaFuncSetAttribute((const void*)tgemm_h<128, 2>,
                         cudaFuncAttributeMaxDynamicSharedMemorySize, SM128);
    cudaFuncSetAttribute((const void*)tgemm_h<128, 4>,
                         cudaFuncAttributeMaxDynamicSharedMemorySize, SM128);
    cudaFuncSetAttribute((const void*)tgemm_h<64, 1>,
                         cudaFuncAttributeMaxDynamicSharedMemorySize, SM64);

    const int M = BB * PP;          // 4096
    const long long zero = 0;

    // ---- prep: merged fp32->fp16 conversion + W1 interleave + b1 reorder ----
    h_copy_all<<<14344, 256>>>(x, Wq, Wk, Wv, Wpv, W1, W2, b1, hb, b1r);

    // 1-3: Q (alpha=0.125) -> qh, K -> kh, V -> vt (transposed)
    {
        dim3 grid(DD / 128, M / 128, 1);
        tgemm_h<128, 1><<<grid, 256, SM128>>>(xh, wqh, nullptr, qh,
            DD, DD, DD, HH * DQK,
            1, zero, zero, zero, zero, zero, zero, 0.125f);
        tgemm_h<128, 1><<<grid, 256, SM128>>>(xh, wkh, nullptr, kh,
            DD, DD, DD, HH * DQK,
            1, zero, zero, zero, zero, zero, zero, 1.0f);
        tgemm_h<128, 2><<<grid, 256, SM128>>>(xh, wvh, nullptr, vt,
            DD, DD, DD, 0,
            1, zero, zero, zero, zero, zero, zero, 1.0f);
    }

    // 4: scores[b,h] = q_bh @ k_bh^T  -> sch (half), batched over 64
    {
        dim3 grid(PP / 128, PP / 128, BB * HH);
        tgemm_h<128, 1><<<grid, 256, SM128>>>(qh, kh, nullptr, sch,
            DQK, HH * DQK, HH * DQK, PP,
            HH,
            (long long)PP * 1024, (long long)DQK,
            (long long)PP * 1024, (long long)DQK,
            (long long)HH * PP * PP, (long long)PP * PP,
            1.0f);
    }

    // 5: mix + prev + softmax -> attn (fp32, d_out) + attnh (half)
    mix_softmax_kernel<<<BB * PP, 512>>>(sch, attn_prev, W_th, attn, attnh);

    // 6: o[b,h] = attn_bh @ vt_bh^T  (NT, BN=64) -> oh (half)
    {
        dim3 grid(1, PP / 128, BB * HH);
        tgemm_h<64, 1><<<grid, 256, SM64>>>(attnh, vt, nullptr, oh,
            PP, PP, PP, HH * DV,
            HH,
            (long long)HH * PP * PP, (long long)PP * PP,
            (long long)HH * DV * PP, (long long)DV * PP,
            (long long)PP * 1024, (long long)DV,
            1.0f);
    }

    // 7: x_sa = o @ Wpv^T  -> float
    {
        dim3 grid(DD / 128, M / 128, 1);
        tgemm_h<128, 0><<<grid, 256, SM128>>>(oh, wpvh, nullptr, xsa,
            HH * DV, HH * DV, HH * DV, DD,
            1, zero, zero, zero, zero, zero, zero, 1.0f);
    }

    // 8: x1 = LN(x + xsa) -> float + half
    add_ln_kernel<1><<<M, 256>>>(x, xsa, ln1g, ln1b, x1, x1h);

    // 9: fused W1 + GLU: t = (a+b)*relu(g+b'), interleaved weights, ldc=2048
    {
        dim3 grid(DMID / 128, M / 128, 1);
        tgemm_h<128, 4><<<grid, 256, SM128>>>(x1h, w1h, b1r, th,
            DD, DD, DD, DMID / 2,
            1, zero, zero, zero, zero, zero, zero, 1.0f);
    }

    // 10: y = t @ W2^T + b2 -> float
    {
        dim3 grid(DD / 128, M / 128, 1);
        tgemm_h<128, 0><<<grid, 256, SM128>>>(th, w2h, b2, yb,
            DMID / 2, DMID / 2, DMID / 2, DD,
            1, zero, zero, zero, zero, zero, zero, 1.0f);
    }

    // 11: out = LN(x1 + y)
    add_ln_kernel<0><<<M, 256>>>(x1, yb, ln2g, ln2b, out, nullptr);
}